// round 8
// baseline (speedup 1.0000x reference)
#include <cuda_runtime.h>
#include <cstdint>

#define BB 4
#define PP 2048
#define EE 4096
#define SS 16
#define KLOG2E 2.885390081777927f   // 2*log2(e)
#define PTILE 4
#define ETILE 256

typedef unsigned long long ull;

// Scratch (precomputed by prep_kernel)
__device__ float  g_pa[PP * SS];     // product @ Wa          [p][s]   (raw)
__device__ float  g_pbT[SS * EE];    // (person @ Wb)^T       [s][e]   (raw)
__device__ float4 g_w2k4[SS * 8];    // [s][jp]: {w,w,w',w'}, w = K*W2[s][j]
__device__ float  g_w3f[SS];         // -2 * W3[j]
__device__ float  g_s3;              // sum_j W3[j]

// ---------------- packed f32x2 helpers ----------------
__device__ __forceinline__ ull pack2(float lo, float hi) {
    ull r; asm("mov.b64 %0,{%1,%2};" : "=l"(r) : "f"(lo), "f"(hi)); return r;
}
__device__ __forceinline__ void unpack2(ull v, float& lo, float& hi) {
    asm("mov.b64 {%0,%1},%2;" : "=f"(lo), "=f"(hi) : "l"(v));
}
__device__ __forceinline__ ull fma2(ull a, ull b, ull c) {
    ull d; asm("fma.rn.f32x2 %0,%1,%2,%3;" : "=l"(d) : "l"(a), "l"(b), "l"(c)); return d;
}
__device__ __forceinline__ ull mul2(ull a, ull b) {
    ull d; asm("mul.rn.f32x2 %0,%1,%2;" : "=l"(d) : "l"(a), "l"(b)); return d;
}
__device__ __forceinline__ ull add2(ull a, ull b) {
    ull d; asm("add.rn.f32x2 %0,%1,%2;" : "=l"(d) : "l"(a), "l"(b)); return d;
}

// Degree-7 odd Taylor tanh, packed f32x2 (R4-validated accuracy: rel_err ~4e-6).
__device__ __forceinline__ ull tanh2(ull x, ull C1, ull C2, ull C3, ull ONE) {
    ull y = mul2(x, x);
    ull p = fma2(C3, y, C2);
    p = fma2(p, y, C1);
    p = fma2(p, y, ONE);
    return mul2(x, p);
}

// r = 1/(2^a + 1), a pre-scaled by 2*log2(e):  tanh = 1 - 2r (folded by caller).
__device__ __forceinline__ float rfun(float a) {
    float e; asm("ex2.approx.f32 %0,%1;" : "=f"(e) : "f"(a));
    float r; asm("rcp.approx.f32 %0,%1;" : "=f"(r) : "f"(e + 1.0f));
    return r;
}

// ---------------- kernel 1: projections + weight folds ----------------
__global__ void prep_kernel(const float* __restrict__ product,
                            const float* __restrict__ person,
                            const float* __restrict__ W1,
                            const float* __restrict__ W2,
                            const float* __restrict__ W3) {
    int idx = blockIdx.x * blockDim.x + threadIdx.x;
    const int totalA  = PP * SS;
    const int totalAB = (PP + EE) * SS;
    if (idx < totalA) {
        int p = idx >> 4, j = idx & 15;
        float acc = 0.f;
#pragma unroll
        for (int s = 0; s < SS; s++)
            acc = fmaf(product[p * SS + s], W1[s * SS + j], acc);
        g_pa[idx] = acc;
    } else if (idx < totalAB) {
        int e = (idx >> 4) - PP, j = idx & 15;
        float acc = 0.f;
#pragma unroll
        for (int s = 0; s < SS; s++)
            acc = fmaf(person[e * SS + s], W1[(SS + s) * SS + j], acc);
        g_pbT[j * EE + e] = acc;   // transposed: [s][e]
    } else {
        int k = idx - totalAB;
        if (k < 256) {
            int s = k >> 4, j = k & 15;
            float v = KLOG2E * W2[k];
            float* w = (float*)g_w2k4;
            int base = (s * 8 + (j >> 1)) * 4 + ((j & 1) << 1);
            w[base] = v; w[base + 1] = v;
        } else if (k < 272) {
            g_w3f[k - 256] = -2.0f * W3[k - 256];
        } else if (k == 272) {
            float sv = 0.f;
#pragma unroll
            for (int j = 0; j < SS; j++) sv += W3[j];
            g_s3 = sv;
        }
    }
}

// ---------------- kernel 2: fused score + broadcast multiply ----------------
// s-STREAMED layer-2: per s, compute packed h1 pair and immediately FMA into
// all 16 packed j-accumulators. Live state = 32 acc regs (vs 64 for the h1
// array in the R3 ordering) -> 6 blocks/SM. Each s's weights touched once
// (broadcast LDS.128), so LDS-per-e matches R3 (not the R2 re-visit trap).
// Per-pp __syncthreads() fence retained (R4/R5 lesson: prevents cross-iter
// pipelining -> spill).
__global__ __launch_bounds__(128, 6)
void adjacency_main(const float* __restrict__ x, float* __restrict__ out) {
    __shared__ ull    v2[SS][ETILE / 2];  // [s][epair]; 16KB
    __shared__ float4 w2s[SS * 8];        // folded K*W2 dup-pairs; 2KB
    __shared__ ull    us2[SS];            // {u_s, u_s} for current p
    __shared__ float2 w3s2[SS / 2];       // {-2W3[2jc], -2W3[2jc+1]}
    __shared__ float  s3s;

    const int tid = threadIdx.x;
    const int eblk = blockIdx.x * ETILE;
    const int p0 = blockIdx.y * PTILE;

    // one-time fills
    w2s[tid] = g_w2k4[tid];
    if (tid < SS / 2)
        w3s2[tid] = make_float2(g_w3f[2 * tid], g_w3f[2 * tid + 1]);
    if (tid == 0) s3s = g_s3;
    {   // v-tile: 16 rows x 256 floats, 16B chunks (coalesced; g_pbT is [s][e])
        const ulonglong2* __restrict__ src = reinterpret_cast<const ulonglong2*>(g_pbT);
        ulonglong2* dst = reinterpret_cast<ulonglong2*>(&v2[0][0]);
#pragma unroll
        for (int i = tid; i < SS * (ETILE / 4); i += 128) {   // 1024 chunks
            int s = i >> 6, q = i & 63;
            dst[s * (ETILE / 4) + q] = src[s * (EE / 4) + (eblk >> 2) + q];
        }
    }

    const ull C1 = pack2(-0.33333334f, -0.33333334f);
    const ull C2 = pack2(0.13333334f, 0.13333334f);
    const ull C3 = pack2(-0.05396825f, -0.05396825f);
    const ull ONE = pack2(1.0f, 1.0f);

    const ulonglong2* __restrict__ w2u = reinterpret_cast<const ulonglong2*>(w2s);
    const ull* __restrict__ x2 = reinterpret_cast<const ull*>(x);
    ull* __restrict__ o2 = reinterpret_cast<ull*>(out);

    for (int pp = 0; pp < PTILE; pp++) {
        const int p = p0 + pp;
        __syncthreads();   // covers one-time fills (pp=0) and us2 reuse (pp>0)
        if (tid < SS) {
            float u = g_pa[p * SS + tid];
            us2[tid] = pack2(u, u);
        }
        __syncthreads();

        // ---- fused layer 1 + layer 2 accumulate, streamed over s ----
        ull acc[SS];
#pragma unroll
        for (int j = 0; j < SS; j++) acc[j] = 0ull;
#pragma unroll
        for (int s = 0; s < SS; s++) {
            ull v = v2[s][tid];                       // LDS.64, conflict-free
            ull h = tanh2(add2(us2[s], v), C1, C2, C3, ONE);
#pragma unroll
            for (int jc = 0; jc < 8; jc++) {
                ulonglong2 w = w2u[s * 8 + jc];       // broadcast LDS.128
                acc[2 * jc]     = fma2(h, w.x, acc[2 * jc]);
                acc[2 * jc + 1] = fma2(h, w.y, acc[2 * jc + 1]);
            }
        }

        // ---- z = S3 - 2 * sum_j r(K*acc_j) * W3_j ----
        float z0 = s3s, z1 = s3s;
#pragma unroll
        for (int jc = 0; jc < 8; jc++) {
            const float2 w3q = w3s2[jc];
            float a, b;
            unpack2(acc[2 * jc], a, b);
            z0 = fmaf(rfun(a), w3q.x, z0);
            z1 = fmaf(rfun(b), w3q.x, z1);
            unpack2(acc[2 * jc + 1], a, b);
            z0 = fmaf(rfun(a), w3q.y, z0);
            z1 = fmaf(rfun(b), w3q.y, z1);
        }

        // ---- leaky relu + out = score * x (8B vectors, 4 batches) ----
        ull sc = pack2(fmaxf(z0, 0.1f * z0), fmaxf(z1, 0.1f * z1));

        unsigned base = (((unsigned)p * EE) + (unsigned)eblk + (unsigned)tid * 2u) >> 1;
        const unsigned bstride = (PP * EE) >> 1;
#pragma unroll
        for (int b = 0; b < BB; b++) {
            o2[base] = mul2(sc, x2[base]);
            base += bstride;
        }
    }
}

extern "C" void kernel_launch(void* const* d_in, const int* in_sizes, int n_in,
                              void* d_out, int out_size) {
    const float* x       = (const float*)d_in[0];
    const float* product = (const float*)d_in[1];
    const float* person  = (const float*)d_in[2];
    const float* W1      = (const float*)d_in[3];
    const float* W2      = (const float*)d_in[4];
    const float* W3      = (const float*)d_in[5];
    float* out = (float*)d_out;

    {
        int total = (PP + EE) * SS + 273;
        int threads = 256;
        int blocks = (total + threads - 1) / threads;
        prep_kernel<<<blocks, threads>>>(product, person, W1, W2, W3);
    }
    {
        dim3 grid(EE / ETILE, PP / PTILE);
        adjacency_main<<<grid, 128>>>(x, out);
    }
}

// round 9
// speedup vs baseline: 1.2544x; 1.2544x over previous
#include <cuda_runtime.h>
#include <cstdint>

#define BB 4
#define PP 2048
#define EE 4096
#define SS 16
#define KLOG2E 2.885390081777927f   // 2*log2(e)
#define PTILE 4
#define ETILE 256

typedef unsigned long long ull;

// Scratch (precomputed by prep_kernel)
__device__ float g_pa[PP * SS];      // product @ Wa          [p][s]   (raw)
__device__ float g_pbT[SS * EE];     // (person @ Wb)^T       [s][e]   (raw)

// Staging for constants (filled by prep, copied into c_cw via D2D memcpy):
//   [0..255]  : {Kw, Kw} dup pairs, index s*16 + j,  w = W2[s][j], K = 2log2(e)
//   [256..263]: {-2*W3[2jc], -2*W3[2jc+1]}
//   [264]     : {s3, s3},  s3 = sum_j W3[j]
#define CW_SIZE 265
__device__ ull g_cw[CW_SIZE];
__constant__ ull c_cw[CW_SIZE];

// ---------------- packed f32x2 helpers ----------------
__device__ __forceinline__ ull pack2(float lo, float hi) {
    ull r; asm("mov.b64 %0,{%1,%2};" : "=l"(r) : "f"(lo), "f"(hi)); return r;
}
__device__ __forceinline__ void unpack2(ull v, float& lo, float& hi) {
    asm("mov.b64 {%0,%1},%2;" : "=f"(lo), "=f"(hi) : "l"(v));
}
__device__ __forceinline__ ull fma2(ull a, ull b, ull c) {
    ull d; asm("fma.rn.f32x2 %0,%1,%2,%3;" : "=l"(d) : "l"(a), "l"(b), "l"(c)); return d;
}
__device__ __forceinline__ ull mul2(ull a, ull b) {
    ull d; asm("mul.rn.f32x2 %0,%1,%2;" : "=l"(d) : "l"(a), "l"(b)); return d;
}
__device__ __forceinline__ ull add2(ull a, ull b) {
    ull d; asm("add.rn.f32x2 %0,%1,%2;" : "=l"(d) : "l"(a), "l"(b)); return d;
}

// Degree-7 odd Taylor tanh, packed f32x2 (validated: rel_err ~4e-6).
__device__ __forceinline__ ull tanh2(ull x, ull C1, ull C2, ull C3, ull ONE) {
    ull y = mul2(x, x);
    ull p = fma2(C3, y, C2);
    p = fma2(p, y, C1);
    p = fma2(p, y, ONE);
    return mul2(x, p);
}

// r = 1/(2^a + 1), a pre-scaled by 2*log2(e):  tanh = 1 - 2r (folded by caller).
__device__ __forceinline__ float rfun(float a) {
    float e; asm("ex2.approx.f32 %0,%1;" : "=f"(e) : "f"(a));
    float r; asm("rcp.approx.f32 %0,%1;" : "=f"(r) : "f"(e + 1.0f));
    return r;
}

// ---------------- kernel 1: projections + constant staging ----------------
__global__ void prep_kernel(const float* __restrict__ product,
                            const float* __restrict__ person,
                            const float* __restrict__ W1,
                            const float* __restrict__ W2,
                            const float* __restrict__ W3) {
    int idx = blockIdx.x * blockDim.x + threadIdx.x;
    const int totalA  = PP * SS;
    const int totalAB = (PP + EE) * SS;
    if (idx < totalA) {
        int p = idx >> 4, j = idx & 15;
        float acc = 0.f;
#pragma unroll
        for (int s = 0; s < SS; s++)
            acc = fmaf(product[p * SS + s], W1[s * SS + j], acc);
        g_pa[idx] = acc;
    } else if (idx < totalAB) {
        int e = (idx >> 4) - PP, j = idx & 15;
        float acc = 0.f;
#pragma unroll
        for (int s = 0; s < SS; s++)
            acc = fmaf(person[e * SS + s], W1[(SS + s) * SS + j], acc);
        g_pbT[j * EE + e] = acc;   // transposed: [s][e]
    } else {
        int k = idx - totalAB;
        if (k < 256) {
            // g_cw[s*16 + j] = {K*W2[s][j]} dup
            float v = KLOG2E * W2[k];
            ull d; asm("mov.b64 %0,{%1,%2};" : "=l"(d) : "f"(v), "f"(v));
            g_cw[k] = d;
        } else if (k < 264) {
            int jc = k - 256;
            float a = -2.0f * W3[2 * jc];
            float b = -2.0f * W3[2 * jc + 1];
            ull d; asm("mov.b64 %0,{%1,%2};" : "=l"(d) : "f"(a), "f"(b));
            g_cw[k] = d;
        } else if (k == 264) {
            float sv = 0.f;
#pragma unroll
            for (int j = 0; j < SS; j++) sv += W3[j];
            ull d; asm("mov.b64 %0,{%1,%2};" : "=l"(d) : "f"(sv), "f"(sv));
            g_cw[k] = d;
        }
    }
}

// ---------------- kernel 2: fused score + broadcast multiply ----------------
// s-streamed (R7 structure: 80 regs, occ 36%), but ALL weights come from
// __constant__ memory (LDCU uniform-const port) instead of shared -> the L1
// shared-port bottleneck (85.7% in R7) disappears. LDS left: v2 only.
// Per-pp __syncthreads() fences retained (R4/R5: they pin live ranges).
__global__ __launch_bounds__(128, 6)
void adjacency_main(const float* __restrict__ x, float* __restrict__ out) {
    __shared__ ull v2[SS][ETILE / 2];   // [s][epair]; 16KB
    __shared__ ull us2[SS];             // {u_s, u_s} for current p

    const int tid = threadIdx.x;
    const int eblk = blockIdx.x * ETILE;
    const int p0 = blockIdx.y * PTILE;

    {   // v-tile: 16 rows x 256 floats, 16B chunks (coalesced; g_pbT is [s][e])
        const ulonglong2* __restrict__ src = reinterpret_cast<const ulonglong2*>(g_pbT);
        ulonglong2* dst = reinterpret_cast<ulonglong2*>(&v2[0][0]);
#pragma unroll
        for (int i = tid; i < SS * (ETILE / 4); i += 128) {   // 1024 chunks
            int s = i >> 6, q = i & 63;
            dst[s * (ETILE / 4) + q] = src[s * (EE / 4) + (eblk >> 2) + q];
        }
    }

    const ull C1 = pack2(-0.33333334f, -0.33333334f);
    const ull C2 = pack2(0.13333334f, 0.13333334f);
    const ull C3 = pack2(-0.05396825f, -0.05396825f);
    const ull ONE = pack2(1.0f, 1.0f);

    const ulonglong2* __restrict__ cw2 = reinterpret_cast<const ulonglong2*>(c_cw);
    const ull* __restrict__ x2 = reinterpret_cast<const ull*>(x);
    ull* __restrict__ o2 = reinterpret_cast<ull*>(out);

    float s3v;
    { float dummy; unpack2(c_cw[264], s3v, dummy); }

    for (int pp = 0; pp < PTILE; pp++) {
        const int p = p0 + pp;
        __syncthreads();   // covers one-time fill (pp=0) and us2 reuse (pp>0)
        if (tid < SS) {
            float u = g_pa[p * SS + tid];
            us2[tid] = pack2(u, u);
        }
        __syncthreads();

        // ---- fused layer 1 + layer 2 accumulate, streamed over s ----
        ull acc[SS];
#pragma unroll
        for (int j = 0; j < SS; j++) acc[j] = 0ull;
#pragma unroll
        for (int s = 0; s < SS; s++) {
            ull v = v2[s][tid];                       // LDS.64, conflict-free
            ull h = tanh2(add2(us2[s], v), C1, C2, C3, ONE);
#pragma unroll
            for (int jc = 0; jc < 8; jc++) {
                ulonglong2 w = cw2[s * 8 + jc];       // LDCU.128, const port
                acc[2 * jc]     = fma2(h, w.x, acc[2 * jc]);
                acc[2 * jc + 1] = fma2(h, w.y, acc[2 * jc + 1]);
            }
        }

        // ---- z = S3 - 2 * sum_j r(K*acc_j) * W3_j ----
        float z0 = s3v, z1 = s3v;
#pragma unroll
        for (int jc = 0; jc < 8; jc++) {
            float w3a, w3b;
            unpack2(c_cw[256 + jc], w3a, w3b);
            float a, b;
            unpack2(acc[2 * jc], a, b);
            z0 = fmaf(rfun(a), w3a, z0);
            z1 = fmaf(rfun(b), w3a, z1);
            unpack2(acc[2 * jc + 1], a, b);
            z0 = fmaf(rfun(a), w3b, z0);
            z1 = fmaf(rfun(b), w3b, z1);
        }

        // ---- leaky relu + out = score * x (8B vectors, 4 batches) ----
        ull sc = pack2(fmaxf(z0, 0.1f * z0), fmaxf(z1, 0.1f * z1));

        unsigned base = (((unsigned)p * EE) + (unsigned)eblk + (unsigned)tid * 2u) >> 1;
        const unsigned bstride = (PP * EE) >> 1;
#pragma unroll
        for (int b = 0; b < BB; b++) {
            o2[base] = mul2(sc, x2[base]);
            base += bstride;
        }
    }
}

extern "C" void kernel_launch(void* const* d_in, const int* in_sizes, int n_in,
                              void* d_out, int out_size) {
    const float* x       = (const float*)d_in[0];
    const float* product = (const float*)d_in[1];
    const float* person  = (const float*)d_in[2];
    const float* W1      = (const float*)d_in[3];
    const float* W2      = (const float*)d_in[4];
    const float* W3      = (const float*)d_in[5];
    float* out = (float*)d_out;

    {
        int total = (PP + EE) * SS + 265;
        int threads = 256;
        int blocks = (total + threads - 1) / threads;
        prep_kernel<<<blocks, threads>>>(product, person, W1, W2, W3);
    }
    {   // stage folded constants into the __constant__ bank (D2D, graph-legal)
        void* dst = nullptr;
        void* src = nullptr;
        cudaGetSymbolAddress(&dst, c_cw);
        cudaGetSymbolAddress(&src, g_cw);
        cudaMemcpyAsync(dst, src, CW_SIZE * sizeof(ull), cudaMemcpyDeviceToDevice);
    }
    {
        dim3 grid(EE / ETILE, PP / PTILE);
        adjacency_main<<<grid, 128>>>(x, out);
    }
}